// round 11
// baseline (speedup 1.0000x reference)
#include <cuda_runtime.h>
#include <math.h>
#include <cstdint>

#define BATCH 256
#define NA    32
#define OBS   128
#define ACT   8
#define DV    128
#define DH    64
#define DO    8
#define S1    132   // padded stride (floats) for 128-wide rows
#define S2    68    // padded stride for 64-wide rows

// ---------------- Kernel A smem (union of t-path / v-path) ----------------
#define A_OFF_STATES 0
#define A_OFF_BUF1   (A_OFF_STATES + NA*S1)
#define A_OFF_BUF2   (A_OFF_BUF1 + NA*S1)
#define A_OFF_W      A_OFF_BUF2                 // t-path only (aliases buf2)
#define A_OFF_ACT    (A_OFF_BUF2 + NA*S1)       // v-path only
#define A_OFF_POL    (A_OFF_ACT + NA*ACT)
#define A_SMEM_FLOATS (A_OFF_POL + NA*ACT)
#define A_SMEM_BYTES  (A_SMEM_FLOATS * 4)

// ---------------- Kernel B smem ----------------
#define B_OFF_W16   0                            // [16][NA]
#define B_OFF_AW1   (B_OFF_W16 + 16*NA)          // [NA][S2]
#define B_OFF_DW1   (B_OFF_AW1 + NA*S2)
#define B_OFF_BW1   (B_OFF_DW1 + NA*S2)          // [16][S2]
#define B_OFF_W2    (B_OFF_BW1 + 16*S2)
#define B_SMEM_FLOATS (B_OFF_W2 + DH*DO)
#define B_SMEM_BYTES  (B_SMEM_FLOATS * 4)

__device__ float g_M[OBS * OBS];            // (Wq @ Wk^T)/sqrt(DK)
__device__ float g_aW1[BATCH * NA * DH];    // avA @ W1   (2 MB)
__device__ float g_dW1[BATCH * NA * DH];    // diff @ W1  (2 MB)

// ---------------------------------------------------------------------------
// M[i][j] = (sum_d Wq[i][d] * Wk[j][d]) / sqrt(128)
// ---------------------------------------------------------------------------
__global__ void compute_M_kernel(const float* __restrict__ Wq,
                                 const float* __restrict__ Wk) {
    __shared__ float qs[16][OBS + 4];
    __shared__ float ks[16][OBS + 4];
    const int i0 = (blockIdx.x & 7) * 16;
    const int j0 = (blockIdx.x >> 3) * 16;
    const int tid = threadIdx.x;
    for (int idx = tid; idx < 16 * 32; idx += 256) {
        int r = idx >> 5, d4 = (idx & 31) * 4;
        *reinterpret_cast<float4*>(&qs[r][d4]) =
            *reinterpret_cast<const float4*>(&Wq[(i0 + r) * OBS + d4]);
        *reinterpret_cast<float4*>(&ks[r][d4]) =
            *reinterpret_cast<const float4*>(&Wk[(j0 + r) * OBS + d4]);
    }
    __syncthreads();
    const int ti = tid >> 4, tj = tid & 15;
    float acc = 0.f;
    #pragma unroll 8
    for (int d = 0; d < OBS; ++d)
        acc = fmaf(qs[ti][d], ks[tj][d], acc);
    g_M[(i0 + ti) * OBS + j0 + tj] = acc * 0.08838834764831845f;
}

// ---------------------------------------------------------------------------
// Kernel A: grid = 2*BATCH. bid&1==0: QK path (t, scores, softmax -> weight).
//                           bid&1==1: V path (avA/diff, aW1/dW1 -> scratch).
// ---------------------------------------------------------------------------
__global__ __launch_bounds__(256, 3)
void critic_partA(const float* __restrict__ states,
                  const float* __restrict__ policies,
                  const float* __restrict__ actions,
                  const float* __restrict__ Wv,
                  const float* __restrict__ W1,
                  float* __restrict__ weight_out)
{
    extern __shared__ float sm[];
    float* s_states = sm + A_OFF_STATES;
    const int b     = blockIdx.x >> 1;
    const bool vpath = (blockIdx.x & 1) != 0;
    const int tid   = threadIdx.x;

    // ---- stage states (both paths) ----
    {
        const float* st_b = states + (size_t)b * NA * OBS;
        for (int idx = tid; idx < NA * OBS / 4; idx += 256) {
            int i = idx >> 5, d4 = (idx & 31) * 4;
            *reinterpret_cast<float4*>(&s_states[i * S1 + d4]) =
                *reinterpret_cast<const float4*>(&st_b[i * OBS + d4]);
        }
    }

    if (!vpath) {
        // QK path: t = states@M ; scores ; softmax -> weight_out
        float* s_t = sm + A_OFF_BUF1;
        float* s_w = sm + A_OFF_W;
        __syncthreads();

        {   // P1-t: 4 rows x 4 cols per thread
            const int r0 = (tid >> 5) * 4;
            const int c0 = (tid & 31) * 4;
            float4 acc[4];
            #pragma unroll
            for (int r = 0; r < 4; ++r) acc[r] = make_float4(0,0,0,0);
            for (int kk = 0; kk < OBS; kk += 4) {
                float4 sv[4];
                #pragma unroll
                for (int r = 0; r < 4; ++r)
                    sv[r] = *reinterpret_cast<const float4*>(&s_states[(r0 + r) * S1 + kk]);
                #pragma unroll
                for (int t = 0; t < 4; ++t) {
                    float4 mq = *reinterpret_cast<const float4*>(&g_M[(kk + t) * OBS + c0]);
                    #pragma unroll
                    for (int r = 0; r < 4; ++r) {
                        float s = reinterpret_cast<const float*>(&sv[r])[t];
                        acc[r].x = fmaf(s, mq.x, acc[r].x);
                        acc[r].y = fmaf(s, mq.y, acc[r].y);
                        acc[r].z = fmaf(s, mq.z, acc[r].z);
                        acc[r].w = fmaf(s, mq.w, acc[r].w);
                    }
                }
            }
            #pragma unroll
            for (int r = 0; r < 4; ++r)
                *reinterpret_cast<float4*>(&s_t[(r0 + r) * S1 + c0]) = acc[r];
        }
        __syncthreads();

        {   // P2a: 2x2 score tile; warp w owns rows 4w..4w+3
            const int i0 = (tid >> 4) * 2;
            const int j0 = (tid & 15) * 2;
            float a00 = 0.f, a01 = 0.f, a10 = 0.f, a11 = 0.f;
            for (int kk = 0; kk < OBS; kk += 4) {
                float4 q0 = *reinterpret_cast<const float4*>(&s_t[ i0      * S1 + kk]);
                float4 q1 = *reinterpret_cast<const float4*>(&s_t[(i0 + 1) * S1 + kk]);
                float4 k0 = *reinterpret_cast<const float4*>(&s_states[ j0      * S1 + kk]);
                float4 k1 = *reinterpret_cast<const float4*>(&s_states[(j0 + 1) * S1 + kk]);
                a00 = fmaf(q0.x, k0.x, fmaf(q0.y, k0.y, fmaf(q0.z, k0.z, fmaf(q0.w, k0.w, a00))));
                a01 = fmaf(q0.x, k1.x, fmaf(q0.y, k1.y, fmaf(q0.z, k1.z, fmaf(q0.w, k1.w, a01))));
                a10 = fmaf(q1.x, k0.x, fmaf(q1.y, k0.y, fmaf(q1.z, k0.z, fmaf(q1.w, k0.w, a10))));
                a11 = fmaf(q1.x, k1.x, fmaf(q1.y, k1.y, fmaf(q1.z, k1.z, fmaf(q1.w, k1.w, a11))));
            }
            s_w[i0 * NA + j0]           = a00;
            s_w[i0 * NA + j0 + 1]       = a01;
            s_w[(i0 + 1) * NA + j0]     = a10;
            s_w[(i0 + 1) * NA + j0 + 1] = a11;
        }
        __syncwarp();

        {   // softmax: warp w owns rows 4w..4w+3 -> weight_out
            const int warp = tid >> 5, lane = tid & 31;
            #pragma unroll
            for (int rr = 0; rr < 4; ++rr) {
                const int row = warp * 4 + rr;
                float v = s_w[row * NA + lane];
                float m = v;
                #pragma unroll
                for (int off = 16; off > 0; off >>= 1)
                    m = fmaxf(m, __shfl_xor_sync(0xffffffffu, m, off));
                float e = expf(v - m);
                float s = e;
                #pragma unroll
                for (int off = 16; off > 0; off >>= 1)
                    s += __shfl_xor_sync(0xffffffffu, s, off);
                weight_out[(size_t)b * NA * NA + row * NA + lane] = e / s;
            }
        }
    } else {
        // V path: avA/diff = tanh(concat@Wv) ; aW1/dW1 -> scratch
        float* s_avA  = sm + A_OFF_BUF1;
        float* s_diff = sm + A_OFF_BUF2;
        float* s_act  = sm + A_OFF_ACT;
        float* s_pol  = sm + A_OFF_POL;

        for (int idx = tid; idx < NA * ACT; idx += 256) {
            s_act[idx] = actions [(size_t)b * NA * ACT + idx];
            s_pol[idx] = policies[(size_t)b * NA * ACT + idx];
        }
        __syncthreads();

        {   // P1-v: 4 rows x 4 cols; sequenced A-then-P to limit live regs
            const int r0 = (tid >> 5) * 4;
            const int c0 = (tid & 31) * 4;
            float4 vAcc[4];
            #pragma unroll
            for (int r = 0; r < 4; ++r) vAcc[r] = make_float4(0,0,0,0);
            for (int kk = 0; kk < OBS; kk += 4) {
                float4 sv[4];
                #pragma unroll
                for (int r = 0; r < 4; ++r)
                    sv[r] = *reinterpret_cast<const float4*>(&s_states[(r0 + r) * S1 + kk]);
                #pragma unroll
                for (int t = 0; t < 4; ++t) {
                    float4 wv = *reinterpret_cast<const float4*>(&Wv[(kk + t) * DV + c0]);
                    #pragma unroll
                    for (int r = 0; r < 4; ++r) {
                        float s = reinterpret_cast<const float*>(&sv[r])[t];
                        vAcc[r].x = fmaf(s, wv.x, vAcc[r].x);
                        vAcc[r].y = fmaf(s, wv.y, vAcc[r].y);
                        vAcc[r].z = fmaf(s, wv.z, vAcc[r].z);
                        vAcc[r].w = fmaf(s, wv.w, vAcc[r].w);
                    }
                }
            }
            {   // actions tail -> avA
                float4 acc[4];
                #pragma unroll
                for (int r = 0; r < 4; ++r) acc[r] = vAcc[r];
                #pragma unroll
                for (int kk = 0; kk < ACT; ++kk) {
                    float4 wv = *reinterpret_cast<const float4*>(&Wv[(OBS + kk) * DV + c0]);
                    #pragma unroll
                    for (int r = 0; r < 4; ++r) {
                        float a = s_act[(r0 + r) * ACT + kk];
                        acc[r].x = fmaf(a, wv.x, acc[r].x);
                        acc[r].y = fmaf(a, wv.y, acc[r].y);
                        acc[r].z = fmaf(a, wv.z, acc[r].z);
                        acc[r].w = fmaf(a, wv.w, acc[r].w);
                    }
                }
                #pragma unroll
                for (int r = 0; r < 4; ++r) {
                    float4 tA;
                    tA.x = tanhf(acc[r].x); tA.y = tanhf(acc[r].y);
                    tA.z = tanhf(acc[r].z); tA.w = tanhf(acc[r].w);
                    *reinterpret_cast<float4*>(&s_avA[(r0 + r) * S1 + c0]) = tA;
                }
            }
            {   // policies tail -> diff = tanh(P) - avA
                float4 acc[4];
                #pragma unroll
                for (int r = 0; r < 4; ++r) acc[r] = vAcc[r];
                #pragma unroll
                for (int kk = 0; kk < ACT; ++kk) {
                    float4 wv = *reinterpret_cast<const float4*>(&Wv[(OBS + kk) * DV + c0]);
                    #pragma unroll
                    for (int r = 0; r < 4; ++r) {
                        float p = s_pol[(r0 + r) * ACT + kk];
                        acc[r].x = fmaf(p, wv.x, acc[r].x);
                        acc[r].y = fmaf(p, wv.y, acc[r].y);
                        acc[r].z = fmaf(p, wv.z, acc[r].z);
                        acc[r].w = fmaf(p, wv.w, acc[r].w);
                    }
                }
                #pragma unroll
                for (int r = 0; r < 4; ++r) {
                    float4 tA = *reinterpret_cast<const float4*>(&s_avA[(r0 + r) * S1 + c0]);
                    float4 dF;
                    dF.x = tanhf(acc[r].x) - tA.x; dF.y = tanhf(acc[r].y) - tA.y;
                    dF.z = tanhf(acc[r].z) - tA.z; dF.w = tanhf(acc[r].w) - tA.w;
                    *reinterpret_cast<float4*>(&s_diff[(r0 + r) * S1 + c0]) = dF;
                }
            }
        }
        __syncthreads();

        {   // P2b: aW1 = avA@W1, dW1 = diff@W1 -> global scratch
            const int j0 = (tid >> 4) * 2;
            const int h0 = (tid & 15) * 4;
            float4 aA0 = make_float4(0,0,0,0), aA1 = make_float4(0,0,0,0);
            float4 aD0 = make_float4(0,0,0,0), aD1 = make_float4(0,0,0,0);
            for (int d = 0; d < DV; d += 4) {
                float4 av0 = *reinterpret_cast<const float4*>(&s_avA [ j0      * S1 + d]);
                float4 av1 = *reinterpret_cast<const float4*>(&s_avA [(j0 + 1) * S1 + d]);
                float4 df0 = *reinterpret_cast<const float4*>(&s_diff[ j0      * S1 + d]);
                float4 df1 = *reinterpret_cast<const float4*>(&s_diff[(j0 + 1) * S1 + d]);
                #pragma unroll
                for (int t = 0; t < 4; ++t) {
                    float4 w1 = *reinterpret_cast<const float4*>(&W1[(d + t) * DH + h0]);
                    float a0 = reinterpret_cast<const float*>(&av0)[t];
                    float a1 = reinterpret_cast<const float*>(&av1)[t];
                    float d0 = reinterpret_cast<const float*>(&df0)[t];
                    float d1 = reinterpret_cast<const float*>(&df1)[t];
                    aA0.x = fmaf(a0, w1.x, aA0.x); aA0.y = fmaf(a0, w1.y, aA0.y);
                    aA0.z = fmaf(a0, w1.z, aA0.z); aA0.w = fmaf(a0, w1.w, aA0.w);
                    aA1.x = fmaf(a1, w1.x, aA1.x); aA1.y = fmaf(a1, w1.y, aA1.y);
                    aA1.z = fmaf(a1, w1.z, aA1.z); aA1.w = fmaf(a1, w1.w, aA1.w);
                    aD0.x = fmaf(d0, w1.x, aD0.x); aD0.y = fmaf(d0, w1.y, aD0.y);
                    aD0.z = fmaf(d0, w1.z, aD0.z); aD0.w = fmaf(d0, w1.w, aD0.w);
                    aD1.x = fmaf(d1, w1.x, aD1.x); aD1.y = fmaf(d1, w1.y, aD1.y);
                    aD1.z = fmaf(d1, w1.z, aD1.z); aD1.w = fmaf(d1, w1.w, aD1.w);
                }
            }
            float* gA = g_aW1 + (size_t)b * NA * DH;
            float* gD = g_dW1 + (size_t)b * NA * DH;
            *reinterpret_cast<float4*>(&gA[ j0      * DH + h0]) = aA0;
            *reinterpret_cast<float4*>(&gA[(j0 + 1) * DH + h0]) = aA1;
            *reinterpret_cast<float4*>(&gD[ j0      * DH + h0]) = aD0;
            *reinterpret_cast<float4*>(&gD[(j0 + 1) * DH + h0]) = aD1;
        }
    }
}

// ---------------------------------------------------------------------------
// Kernel B: grid = 2*BATCH. CTA = (b, a-half). P4 + P5 for 16 a-rows.
// ---------------------------------------------------------------------------
__global__ __launch_bounds__(256)
void critic_partB(const float* __restrict__ W2,
                  const float* __restrict__ weight_in,
                  float* __restrict__ value_out)
{
    extern __shared__ float sm[];
    float* s_w16 = sm + B_OFF_W16;   // [16][NA]
    float* s_aW1 = sm + B_OFF_AW1;   // [NA][S2]
    float* s_dW1 = sm + B_OFF_DW1;
    float* s_bW1 = sm + B_OFF_BW1;   // [16][S2]
    float* s_W2  = sm + B_OFF_W2;

    const int b     = blockIdx.x >> 1;
    const int arow0 = (blockIdx.x & 1) * 16;
    const int tid   = threadIdx.x;

    // ---- stage ----
    {
        const float* wsrc = weight_in + (size_t)b * NA * NA + arow0 * NA;
        for (int idx = tid; idx < 16 * NA / 4; idx += 256)
            *reinterpret_cast<float4*>(&s_w16[idx * 4]) =
                *reinterpret_cast<const float4*>(&wsrc[idx * 4]);
        const float* gA = g_aW1 + (size_t)b * NA * DH;
        const float* gD = g_dW1 + (size_t)b * NA * DH;
        for (int idx = tid; idx < NA * DH / 4; idx += 256) {
            int j = idx >> 4, h4 = (idx & 15) * 4;
            *reinterpret_cast<float4*>(&s_aW1[j * S2 + h4]) =
                *reinterpret_cast<const float4*>(&gA[j * DH + h4]);
            *reinterpret_cast<float4*>(&s_dW1[j * S2 + h4]) =
                *reinterpret_cast<const float4*>(&gD[j * DH + h4]);
        }
        for (int idx = tid; idx < DH * DO; idx += 256) s_W2[idx] = W2[idx];
    }
    __syncthreads();

    // ---- P4: bW1[a'] = sum_j w16[a'][j] * aW1[j]  (16 x 64) ----
    {
        const int a  = tid >> 4;          // 0..15
        const int h0 = (tid & 15) * 4;
        float4 acc = make_float4(0,0,0,0);
        #pragma unroll
        for (int j = 0; j < NA; j += 4) {
            float4 wq = *reinterpret_cast<const float4*>(&s_w16[a * NA + j]);
            #pragma unroll
            for (int t = 0; t < 4; ++t) {
                float4 aw = *reinterpret_cast<const float4*>(&s_aW1[(j + t) * S2 + h0]);
                float v = reinterpret_cast<const float*>(&wq)[t];
                acc.x = fmaf(v, aw.x, acc.x); acc.y = fmaf(v, aw.y, acc.y);
                acc.z = fmaf(v, aw.z, acc.z); acc.w = fmaf(v, aw.w, acc.w);
            }
        }
        *reinterpret_cast<float4*>(&s_bW1[a * S2 + h0]) = acc;
    }
    __syncthreads();

    // ---- P5: 2 pairs per thread: rows {a', a'+8}, c = tid&31 ----
    {
        const int a0 = tid >> 5;      // 0..7
        const int c  = tid & 31;
        float wk[2];
        wk[0] = s_w16[ a0      * NA + c];
        wk[1] = s_w16[(a0 + 8) * NA + c];

        float4 accL[2], accH[2];
        #pragma unroll
        for (int k = 0; k < 2; ++k) {
            accL[k] = make_float4(0,0,0,0);
            accH[k] = make_float4(0,0,0,0);
        }
        for (int h = 0; h < DH; h += 4) {
            float4 dq  = *reinterpret_cast<const float4*>(&s_dW1[c * S2 + h]);
            float4 bq0 = *reinterpret_cast<const float4*>(&s_bW1[ a0      * S2 + h]);
            float4 bq1 = *reinterpret_cast<const float4*>(&s_bW1[(a0 + 8) * S2 + h]);
            #pragma unroll
            for (int t = 0; t < 4; ++t) {
                float4 w2lo = *reinterpret_cast<const float4*>(&s_W2[(h + t) * DO]);
                float4 w2hi = *reinterpret_cast<const float4*>(&s_W2[(h + t) * DO + 4]);
                float dqt = reinterpret_cast<const float*>(&dq)[t];

                float x0 = fmaf(wk[0], dqt, reinterpret_cast<const float*>(&bq0)[t]);
                x0 = fmaxf(x0, 0.01f * x0);
                accL[0].x = fmaf(x0, w2lo.x, accL[0].x);
                accL[0].y = fmaf(x0, w2lo.y, accL[0].y);
                accL[0].z = fmaf(x0, w2lo.z, accL[0].z);
                accL[0].w = fmaf(x0, w2lo.w, accL[0].w);
                accH[0].x = fmaf(x0, w2hi.x, accH[0].x);
                accH[0].y = fmaf(x0, w2hi.y, accH[0].y);
                accH[0].z = fmaf(x0, w2hi.z, accH[0].z);
                accH[0].w = fmaf(x0, w2hi.w, accH[0].w);

                float x1 = fmaf(wk[1], dqt, reinterpret_cast<const float*>(&bq1)[t]);
                x1 = fmaxf(x1, 0.01f * x1);
                accL[1].x = fmaf(x1, w2lo.x, accL[1].x);
                accL[1].y = fmaf(x1, w2lo.y, accL[1].y);
                accL[1].z = fmaf(x1, w2lo.z, accL[1].z);
                accL[1].w = fmaf(x1, w2lo.w, accL[1].w);
                accH[1].x = fmaf(x1, w2hi.x, accH[1].x);
                accH[1].y = fmaf(x1, w2hi.y, accH[1].y);
                accH[1].z = fmaf(x1, w2hi.z, accH[1].z);
                accH[1].w = fmaf(x1, w2hi.w, accH[1].w);
            }
        }
        #pragma unroll
        for (int k = 0; k < 2; ++k) {
            int a_global = arow0 + a0 + 8 * k;
            float4* outp = reinterpret_cast<float4*>(
                value_out + (((size_t)b * NA + a_global) * NA + c) * DO);
            outp[0] = accL[k];
            outp[1] = accH[k];
        }
    }
}

extern "C" void kernel_launch(void* const* d_in, const int* in_sizes, int n_in,
                              void* d_out, int out_size) {
    const float* states   = (const float*)d_in[0];
    const float* policies = (const float*)d_in[1];
    const float* actions  = (const float*)d_in[2];
    const float* Wk       = (const float*)d_in[3];
    const float* Wq       = (const float*)d_in[4];
    const float* Wv       = (const float*)d_in[5];
    const float* W1       = (const float*)d_in[6];
    const float* W2       = (const float*)d_in[7];

    float* value_out  = (float*)d_out;                              // [B,N,N,8]
    float* weight_out = value_out + (size_t)BATCH * NA * NA * DO;   // [B,N,N]

    compute_M_kernel<<<64, 256>>>(Wq, Wk);

    cudaFuncSetAttribute(critic_partA,
                         cudaFuncAttributeMaxDynamicSharedMemorySize, A_SMEM_BYTES);
    critic_partA<<<2 * BATCH, 256, A_SMEM_BYTES>>>(
        states, policies, actions, Wv, W1, weight_out);

    cudaFuncSetAttribute(critic_partB,
                         cudaFuncAttributeMaxDynamicSharedMemorySize, B_SMEM_BYTES);
    critic_partB<<<2 * BATCH, 256, B_SMEM_BYTES>>>(W2, weight_out, value_out);
}

// round 12
// speedup vs baseline: 1.0317x; 1.0317x over previous
#include <cuda_runtime.h>
#include <math.h>
#include <cstdint>

#define BATCH 256
#define NA    32
#define OBS   128
#define ACT   8
#define DV    128
#define DH    64
#define DO    8
#define S1    132   // padded stride (floats) for 128-wide rows
#define S2    68    // padded stride for 64-wide rows

// ---------------- Kernel A smem (union of t-path / v-path) ----------------
#define A_OFF_STATES 0
#define A_OFF_BUF1   (A_OFF_STATES + NA*S1)
#define A_OFF_BUF2   (A_OFF_BUF1 + NA*S1)
#define A_OFF_W      A_OFF_BUF2                 // t-path only (aliases buf2)
#define A_OFF_ACT    (A_OFF_BUF2 + NA*S1)       // v-path only
#define A_OFF_POL    (A_OFF_ACT + NA*ACT)
#define A_SMEM_FLOATS (A_OFF_POL + NA*ACT)
#define A_SMEM_BYTES  (A_SMEM_FLOATS * 4)

// ---------------- Kernel B smem (one CTA per batch) ----------------
#define B_OFF_W     0                            // [NA][NA]
#define B_OFF_AW1   (B_OFF_W + NA*NA)            // [NA][S2]
#define B_OFF_DW1   (B_OFF_AW1 + NA*S2)
#define B_OFF_BW1   (B_OFF_DW1 + NA*S2)          // [NA][S2]
#define B_OFF_W2    (B_OFF_BW1 + NA*S2)
#define B_SMEM_FLOATS (B_OFF_W2 + DH*DO)
#define B_SMEM_BYTES  (B_SMEM_FLOATS * 4)

__device__ float g_M[OBS * OBS];            // (Wq @ Wk^T)/sqrt(DK)
__device__ float g_aW1[BATCH * NA * DH];    // avA @ W1   (2 MB)
__device__ float g_dW1[BATCH * NA * DH];    // diff @ W1  (2 MB)

// ---------------------------------------------------------------------------
// M[i][j] = (sum_d Wq[i][d] * Wk[j][d]) / sqrt(128)
// ---------------------------------------------------------------------------
__global__ void compute_M_kernel(const float* __restrict__ Wq,
                                 const float* __restrict__ Wk) {
    __shared__ float qs[16][OBS + 4];
    __shared__ float ks[16][OBS + 4];
    const int i0 = (blockIdx.x & 7) * 16;
    const int j0 = (blockIdx.x >> 3) * 16;
    const int tid = threadIdx.x;
    for (int idx = tid; idx < 16 * 32; idx += 256) {
        int r = idx >> 5, d4 = (idx & 31) * 4;
        *reinterpret_cast<float4*>(&qs[r][d4]) =
            *reinterpret_cast<const float4*>(&Wq[(i0 + r) * OBS + d4]);
        *reinterpret_cast<float4*>(&ks[r][d4]) =
            *reinterpret_cast<const float4*>(&Wk[(j0 + r) * OBS + d4]);
    }
    __syncthreads();
    const int ti = tid >> 4, tj = tid & 15;
    float acc = 0.f;
    #pragma unroll 8
    for (int d = 0; d < OBS; ++d)
        acc = fmaf(qs[ti][d], ks[tj][d], acc);
    g_M[(i0 + ti) * OBS + j0 + tj] = acc * 0.08838834764831845f;
}

// ---------------------------------------------------------------------------
// Kernel A: grid = 2*BATCH. bid&1==0: QK path (t, scores, softmax -> weight).
//                           bid&1==1: V path (avA/diff, aW1/dW1 -> scratch).
// launch_bounds(256, 2): NO register cap below ~128 — the R11 (256,3) cap to
// 84 regs forced spills in the V path and killed it.
// ---------------------------------------------------------------------------
__global__ __launch_bounds__(256, 2)
void critic_partA(const float* __restrict__ states,
                  const float* __restrict__ policies,
                  const float* __restrict__ actions,
                  const float* __restrict__ Wv,
                  const float* __restrict__ W1,
                  float* __restrict__ weight_out)
{
    extern __shared__ float sm[];
    float* s_states = sm + A_OFF_STATES;
    const int b     = blockIdx.x >> 1;
    const bool vpath = (blockIdx.x & 1) != 0;
    const int tid   = threadIdx.x;

    // ---- stage states (both paths) ----
    {
        const float* st_b = states + (size_t)b * NA * OBS;
        for (int idx = tid; idx < NA * OBS / 4; idx += 256) {
            int i = idx >> 5, d4 = (idx & 31) * 4;
            *reinterpret_cast<float4*>(&s_states[i * S1 + d4]) =
                *reinterpret_cast<const float4*>(&st_b[i * OBS + d4]);
        }
    }

    if (!vpath) {
        // QK path: t = states@M ; scores ; softmax -> weight_out
        float* s_t = sm + A_OFF_BUF1;
        float* s_w = sm + A_OFF_W;
        __syncthreads();

        {   // P1-t: 4 rows x 4 cols per thread
            const int r0 = (tid >> 5) * 4;
            const int c0 = (tid & 31) * 4;
            float4 acc[4];
            #pragma unroll
            for (int r = 0; r < 4; ++r) acc[r] = make_float4(0,0,0,0);
            for (int kk = 0; kk < OBS; kk += 4) {
                float4 sv[4];
                #pragma unroll
                for (int r = 0; r < 4; ++r)
                    sv[r] = *reinterpret_cast<const float4*>(&s_states[(r0 + r) * S1 + kk]);
                #pragma unroll
                for (int t = 0; t < 4; ++t) {
                    float4 mq = *reinterpret_cast<const float4*>(&g_M[(kk + t) * OBS + c0]);
                    #pragma unroll
                    for (int r = 0; r < 4; ++r) {
                        float s = reinterpret_cast<const float*>(&sv[r])[t];
                        acc[r].x = fmaf(s, mq.x, acc[r].x);
                        acc[r].y = fmaf(s, mq.y, acc[r].y);
                        acc[r].z = fmaf(s, mq.z, acc[r].z);
                        acc[r].w = fmaf(s, mq.w, acc[r].w);
                    }
                }
            }
            #pragma unroll
            for (int r = 0; r < 4; ++r)
                *reinterpret_cast<float4*>(&s_t[(r0 + r) * S1 + c0]) = acc[r];
        }
        __syncthreads();

        {   // P2a: 2x2 score tile; warp w owns rows 4w..4w+3
            const int i0 = (tid >> 4) * 2;
            const int j0 = (tid & 15) * 2;
            float a00 = 0.f, a01 = 0.f, a10 = 0.f, a11 = 0.f;
            for (int kk = 0; kk < OBS; kk += 4) {
                float4 q0 = *reinterpret_cast<const float4*>(&s_t[ i0      * S1 + kk]);
                float4 q1 = *reinterpret_cast<const float4*>(&s_t[(i0 + 1) * S1 + kk]);
                float4 k0 = *reinterpret_cast<const float4*>(&s_states[ j0      * S1 + kk]);
                float4 k1 = *reinterpret_cast<const float4*>(&s_states[(j0 + 1) * S1 + kk]);
                a00 = fmaf(q0.x, k0.x, fmaf(q0.y, k0.y, fmaf(q0.z, k0.z, fmaf(q0.w, k0.w, a00))));
                a01 = fmaf(q0.x, k1.x, fmaf(q0.y, k1.y, fmaf(q0.z, k1.z, fmaf(q0.w, k1.w, a01))));
                a10 = fmaf(q1.x, k0.x, fmaf(q1.y, k0.y, fmaf(q1.z, k0.z, fmaf(q1.w, k0.w, a10))));
                a11 = fmaf(q1.x, k1.x, fmaf(q1.y, k1.y, fmaf(q1.z, k1.z, fmaf(q1.w, k1.w, a11))));
            }
            s_w[i0 * NA + j0]           = a00;
            s_w[i0 * NA + j0 + 1]       = a01;
            s_w[(i0 + 1) * NA + j0]     = a10;
            s_w[(i0 + 1) * NA + j0 + 1] = a11;
        }
        __syncwarp();

        {   // softmax: warp w owns rows 4w..4w+3 -> weight_out
            const int warp = tid >> 5, lane = tid & 31;
            #pragma unroll
            for (int rr = 0; rr < 4; ++rr) {
                const int row = warp * 4 + rr;
                float v = s_w[row * NA + lane];
                float m = v;
                #pragma unroll
                for (int off = 16; off > 0; off >>= 1)
                    m = fmaxf(m, __shfl_xor_sync(0xffffffffu, m, off));
                float e = expf(v - m);
                float s = e;
                #pragma unroll
                for (int off = 16; off > 0; off >>= 1)
                    s += __shfl_xor_sync(0xffffffffu, s, off);
                weight_out[(size_t)b * NA * NA + row * NA + lane] = e / s;
            }
        }
    } else {
        // V path: avA/diff = tanh(concat@Wv) ; aW1/dW1 -> scratch
        float* s_avA  = sm + A_OFF_BUF1;
        float* s_diff = sm + A_OFF_BUF2;
        float* s_act  = sm + A_OFF_ACT;
        float* s_pol  = sm + A_OFF_POL;

        for (int idx = tid; idx < NA * ACT; idx += 256) {
            s_act[idx] = actions [(size_t)b * NA * ACT + idx];
            s_pol[idx] = policies[(size_t)b * NA * ACT + idx];
        }
        __syncthreads();

        {   // P1-v: 4 rows x 4 cols
            const int r0 = (tid >> 5) * 4;
            const int c0 = (tid & 31) * 4;
            float4 vAcc[4];
            #pragma unroll
            for (int r = 0; r < 4; ++r) vAcc[r] = make_float4(0,0,0,0);
            for (int kk = 0; kk < OBS; kk += 4) {
                float4 sv[4];
                #pragma unroll
                for (int r = 0; r < 4; ++r)
                    sv[r] = *reinterpret_cast<const float4*>(&s_states[(r0 + r) * S1 + kk]);
                #pragma unroll
                for (int t = 0; t < 4; ++t) {
                    float4 wv = *reinterpret_cast<const float4*>(&Wv[(kk + t) * DV + c0]);
                    #pragma unroll
                    for (int r = 0; r < 4; ++r) {
                        float s = reinterpret_cast<const float*>(&sv[r])[t];
                        vAcc[r].x = fmaf(s, wv.x, vAcc[r].x);
                        vAcc[r].y = fmaf(s, wv.y, vAcc[r].y);
                        vAcc[r].z = fmaf(s, wv.z, vAcc[r].z);
                        vAcc[r].w = fmaf(s, wv.w, vAcc[r].w);
                    }
                }
            }
            {   // actions tail -> avA
                float4 acc[4];
                #pragma unroll
                for (int r = 0; r < 4; ++r) acc[r] = vAcc[r];
                #pragma unroll
                for (int kk = 0; kk < ACT; ++kk) {
                    float4 wv = *reinterpret_cast<const float4*>(&Wv[(OBS + kk) * DV + c0]);
                    #pragma unroll
                    for (int r = 0; r < 4; ++r) {
                        float a = s_act[(r0 + r) * ACT + kk];
                        acc[r].x = fmaf(a, wv.x, acc[r].x);
                        acc[r].y = fmaf(a, wv.y, acc[r].y);
                        acc[r].z = fmaf(a, wv.z, acc[r].z);
                        acc[r].w = fmaf(a, wv.w, acc[r].w);
                    }
                }
                #pragma unroll
                for (int r = 0; r < 4; ++r) {
                    float4 tA;
                    tA.x = tanhf(acc[r].x); tA.y = tanhf(acc[r].y);
                    tA.z = tanhf(acc[r].z); tA.w = tanhf(acc[r].w);
                    *reinterpret_cast<float4*>(&s_avA[(r0 + r) * S1 + c0]) = tA;
                }
            }
            {   // policies tail -> diff = tanh(P) - avA
                float4 acc[4];
                #pragma unroll
                for (int r = 0; r < 4; ++r) acc[r] = vAcc[r];
                #pragma unroll
                for (int kk = 0; kk < ACT; ++kk) {
                    float4 wv = *reinterpret_cast<const float4*>(&Wv[(OBS + kk) * DV + c0]);
                    #pragma unroll
                    for (int r = 0; r < 4; ++r) {
                        float p = s_pol[(r0 + r) * ACT + kk];
                        acc[r].x = fmaf(p, wv.x, acc[r].x);
                        acc[r].y = fmaf(p, wv.y, acc[r].y);
                        acc[r].z = fmaf(p, wv.z, acc[r].z);
                        acc[r].w = fmaf(p, wv.w, acc[r].w);
                    }
                }
                #pragma unroll
                for (int r = 0; r < 4; ++r) {
                    float4 tA = *reinterpret_cast<const float4*>(&s_avA[(r0 + r) * S1 + c0]);
                    float4 dF;
                    dF.x = tanhf(acc[r].x) - tA.x; dF.y = tanhf(acc[r].y) - tA.y;
                    dF.z = tanhf(acc[r].z) - tA.z; dF.w = tanhf(acc[r].w) - tA.w;
                    *reinterpret_cast<float4*>(&s_diff[(r0 + r) * S1 + c0]) = dF;
                }
            }
        }
        __syncthreads();

        {   // P2b: aW1 = avA@W1, dW1 = diff@W1 -> global scratch
            const int j0 = (tid >> 4) * 2;
            const int h0 = (tid & 15) * 4;
            float4 aA0 = make_float4(0,0,0,0), aA1 = make_float4(0,0,0,0);
            float4 aD0 = make_float4(0,0,0,0), aD1 = make_float4(0,0,0,0);
            for (int d = 0; d < DV; d += 4) {
                float4 av0 = *reinterpret_cast<const float4*>(&s_avA [ j0      * S1 + d]);
                float4 av1 = *reinterpret_cast<const float4*>(&s_avA [(j0 + 1) * S1 + d]);
                float4 df0 = *reinterpret_cast<const float4*>(&s_diff[ j0      * S1 + d]);
                float4 df1 = *reinterpret_cast<const float4*>(&s_diff[(j0 + 1) * S1 + d]);
                #pragma unroll
                for (int t = 0; t < 4; ++t) {
                    float4 w1 = *reinterpret_cast<const float4*>(&W1[(d + t) * DH + h0]);
                    float a0 = reinterpret_cast<const float*>(&av0)[t];
                    float a1 = reinterpret_cast<const float*>(&av1)[t];
                    float d0 = reinterpret_cast<const float*>(&df0)[t];
                    float d1 = reinterpret_cast<const float*>(&df1)[t];
                    aA0.x = fmaf(a0, w1.x, aA0.x); aA0.y = fmaf(a0, w1.y, aA0.y);
                    aA0.z = fmaf(a0, w1.z, aA0.z); aA0.w = fmaf(a0, w1.w, aA0.w);
                    aA1.x = fmaf(a1, w1.x, aA1.x); aA1.y = fmaf(a1, w1.y, aA1.y);
                    aA1.z = fmaf(a1, w1.z, aA1.z); aA1.w = fmaf(a1, w1.w, aA1.w);
                    aD0.x = fmaf(d0, w1.x, aD0.x); aD0.y = fmaf(d0, w1.y, aD0.y);
                    aD0.z = fmaf(d0, w1.z, aD0.z); aD0.w = fmaf(d0, w1.w, aD0.w);
                    aD1.x = fmaf(d1, w1.x, aD1.x); aD1.y = fmaf(d1, w1.y, aD1.y);
                    aD1.z = fmaf(d1, w1.z, aD1.z); aD1.w = fmaf(d1, w1.w, aD1.w);
                }
            }
            float* gA = g_aW1 + (size_t)b * NA * DH;
            float* gD = g_dW1 + (size_t)b * NA * DH;
            *reinterpret_cast<float4*>(&gA[ j0      * DH + h0]) = aA0;
            *reinterpret_cast<float4*>(&gA[(j0 + 1) * DH + h0]) = aA1;
            *reinterpret_cast<float4*>(&gD[ j0      * DH + h0]) = aD0;
            *reinterpret_cast<float4*>(&gD[(j0 + 1) * DH + h0]) = aD1;
        }
    }
}

// ---------------------------------------------------------------------------
// Kernel B: grid = BATCH (one CTA per batch). Stage once; P4 + P5 (R5 maps).
// ---------------------------------------------------------------------------
__global__ __launch_bounds__(256, 2)
void critic_partB(const float* __restrict__ W2,
                  const float* __restrict__ weight_in,
                  float* __restrict__ value_out)
{
    extern __shared__ float sm[];
    float* s_w   = sm + B_OFF_W;     // [NA][NA]
    float* s_aW1 = sm + B_OFF_AW1;   // [NA][S2]
    float* s_dW1 = sm + B_OFF_DW1;
    float* s_bW1 = sm + B_OFF_BW1;   // [NA][S2]
    float* s_W2  = sm + B_OFF_W2;

    const int b   = blockIdx.x;
    const int tid = threadIdx.x;

    // ---- stage ----
    {
        const float* wsrc = weight_in + (size_t)b * NA * NA;
        for (int idx = tid; idx < NA * NA / 4; idx += 256)
            *reinterpret_cast<float4*>(&s_w[idx * 4]) =
                *reinterpret_cast<const float4*>(&wsrc[idx * 4]);
        const float* gA = g_aW1 + (size_t)b * NA * DH;
        const float* gD = g_dW1 + (size_t)b * NA * DH;
        for (int idx = tid; idx < NA * DH / 4; idx += 256) {
            int j = idx >> 4, h4 = (idx & 15) * 4;
            *reinterpret_cast<float4*>(&s_aW1[j * S2 + h4]) =
                *reinterpret_cast<const float4*>(&gA[j * DH + h4]);
            *reinterpret_cast<float4*>(&s_dW1[j * S2 + h4]) =
                *reinterpret_cast<const float4*>(&gD[j * DH + h4]);
        }
        for (int idx = tid; idx < DH * DO; idx += 256) s_W2[idx] = W2[idx];
    }
    __syncthreads();

    // ---- P4: bW1 = w @ aW1   [32 x 64]  (R5 mapping) ----
    {
        const int a0 = (tid >> 4) * 2;
        const int h0 = (tid & 15) * 4;
        float4 acc0 = make_float4(0,0,0,0), acc1 = make_float4(0,0,0,0);
        #pragma unroll
        for (int j = 0; j < NA; j += 4) {
            float4 w0 = *reinterpret_cast<const float4*>(&s_w[ a0      * NA + j]);
            float4 w1 = *reinterpret_cast<const float4*>(&s_w[(a0 + 1) * NA + j]);
            #pragma unroll
            for (int t = 0; t < 4; ++t) {
                float4 aw = *reinterpret_cast<const float4*>(&s_aW1[(j + t) * S2 + h0]);
                float v0 = reinterpret_cast<const float*>(&w0)[t];
                float v1 = reinterpret_cast<const float*>(&w1)[t];
                acc0.x = fmaf(v0, aw.x, acc0.x); acc0.y = fmaf(v0, aw.y, acc0.y);
                acc0.z = fmaf(v0, aw.z, acc0.z); acc0.w = fmaf(v0, aw.w, acc0.w);
                acc1.x = fmaf(v1, aw.x, acc1.x); acc1.y = fmaf(v1, aw.y, acc1.y);
                acc1.z = fmaf(v1, aw.z, acc1.z); acc1.w = fmaf(v1, aw.w, acc1.w);
            }
        }
        *reinterpret_cast<float4*>(&s_bW1[ a0      * S2 + h0]) = acc0;
        *reinterpret_cast<float4*>(&s_bW1[(a0 + 1) * S2 + h0]) = acc1;
    }
    __syncthreads();

    // ---- P5: 4 pairs per thread (R5 mapping): rows {a0+8k}, c = tid&31 ----
    {
        const int a0 = tid >> 5;      // 0..7
        const int c  = tid & 31;
        float wk[4];
        #pragma unroll
        for (int k = 0; k < 4; ++k) wk[k] = s_w[(a0 + 8 * k) * NA + c];

        float4 accL[4], accH[4];
        #pragma unroll
        for (int k = 0; k < 4; ++k) {
            accL[k] = make_float4(0,0,0,0);
            accH[k] = make_float4(0,0,0,0);
        }
        for (int h = 0; h < DH; h += 4) {
            float4 dq = *reinterpret_cast<const float4*>(&s_dW1[c * S2 + h]);
            float4 w2lo[4], w2hi[4];
            #pragma unroll
            for (int t = 0; t < 4; ++t) {
                w2lo[t] = *reinterpret_cast<const float4*>(&s_W2[(h + t) * DO]);
                w2hi[t] = *reinterpret_cast<const float4*>(&s_W2[(h + t) * DO + 4]);
            }
            #pragma unroll
            for (int k = 0; k < 4; ++k) {
                float4 bq = *reinterpret_cast<const float4*>(&s_bW1[(a0 + 8 * k) * S2 + h]);
                #pragma unroll
                for (int t = 0; t < 4; ++t) {
                    float x = fmaf(wk[k],
                                   reinterpret_cast<const float*>(&dq)[t],
                                   reinterpret_cast<const float*>(&bq)[t]);
                    x = fmaxf(x, 0.01f * x);   // leaky_relu(0.01)
                    accL[k].x = fmaf(x, w2lo[t].x, accL[k].x);
                    accL[k].y = fmaf(x, w2lo[t].y, accL[k].y);
                    accL[k].z = fmaf(x, w2lo[t].z, accL[k].z);
                    accL[k].w = fmaf(x, w2lo[t].w, accL[k].w);
                    accH[k].x = fmaf(x, w2hi[t].x, accH[k].x);
                    accH[k].y = fmaf(x, w2hi[t].y, accH[k].y);
                    accH[k].z = fmaf(x, w2hi[t].z, accH[k].z);
                    accH[k].w = fmaf(x, w2hi[t].w, accH[k].w);
                }
            }
        }
        #pragma unroll
        for (int k = 0; k < 4; ++k) {
            float4* outp = reinterpret_cast<float4*>(
                value_out + (((size_t)b * NA + (a0 + 8 * k)) * NA + c) * DO);
            outp[0] = accL[k];
            outp[1] = accH[k];
        }
    }
}

extern "C" void kernel_launch(void* const* d_in, const int* in_sizes, int n_in,
                              void* d_out, int out_size) {
    const float* states   = (const float*)d_in[0];
    const float* policies = (const float*)d_in[1];
    const float* actions  = (const float*)d_in[2];
    const float* Wk       = (const float*)d_in[3];
    const float* Wq       = (const float*)d_in[4];
    const float* Wv       = (const float*)d_in[5];
    const float* W1       = (const float*)d_in[6];
    const float* W2       = (const float*)d_in[7];

    float* value_out  = (float*)d_out;                              // [B,N,N,8]
    float* weight_out = value_out + (size_t)BATCH * NA * NA * DO;   // [B,N,N]

    compute_M_kernel<<<64, 256>>>(Wq, Wk);

    cudaFuncSetAttribute(critic_partA,
                         cudaFuncAttributeMaxDynamicSharedMemorySize, A_SMEM_BYTES);
    critic_partA<<<2 * BATCH, 256, A_SMEM_BYTES>>>(
        states, policies, actions, Wv, W1, weight_out);

    cudaFuncSetAttribute(critic_partB,
                         cudaFuncAttributeMaxDynamicSharedMemorySize, B_SMEM_BYTES);
    critic_partB<<<BATCH, 256, B_SMEM_BYTES>>>(W2, weight_out, value_out);
}

// round 13
// speedup vs baseline: 1.0700x; 1.0371x over previous
#include <cuda_runtime.h>
#include <math.h>
#include <cstdint>

#define BATCH 256
#define NA    32
#define OBS   128
#define ACT   8
#define DV    128
#define DH    64
#define DO    8
#define S1    132   // padded stride (floats) for 128-wide rows
#define S2    68    // padded stride for 64-wide rows

// ---- SMEM layout (floats) ----
#define OFF_STATES 0
#define OFF_T      (OFF_STATES + NA*S1)
#define OFF_AVA    (OFF_T + NA*S1)
#define OFF_DIFF   (OFF_AVA + NA*S1)
#define OFF_W      (OFF_DIFF + NA*S1)
#define OFF_AW1    (OFF_W + NA*NA)
#define OFF_DW1    (OFF_AW1 + NA*S2)
#define OFF_BW1    (OFF_DW1 + NA*S2)
#define OFF_ACT    (OFF_BW1 + NA*S2)
#define OFF_POL    (OFF_ACT + NA*ACT)
#define OFF_W2     (OFF_POL + NA*ACT)
#define SMEM_FLOATS (OFF_W2 + DH*DO)
#define SMEM_BYTES  (SMEM_FLOATS * 4)

__device__ float g_M[OBS * OBS];   // (Wq @ Wk^T)/sqrt(DK), built in-kernel
__device__ int   g_cnt;            // arrival counter, memset to 0 pre-launch

// ---------------------------------------------------------------------------
// Single fused kernel. Grid = 256 (one CTA per batch), 256 threads, 2 CTAs/SM.
// All 256 CTAs are co-resident in wave 1 (148 SMs x 2 slots = 296 >= 256), so
// the produce-M / spin-consume handshake cannot deadlock.
// ---------------------------------------------------------------------------
__global__ __launch_bounds__(256, 2)
void critic_kernel(const float* __restrict__ states,
                   const float* __restrict__ policies,
                   const float* __restrict__ actions,
                   const float* __restrict__ Wq,
                   const float* __restrict__ Wk,
                   const float* __restrict__ Wv,
                   const float* __restrict__ W1,
                   const float* __restrict__ W2,
                   float* __restrict__ value_out,
                   float* __restrict__ weight_out)
{
    extern __shared__ float sm[];
    float* s_states = sm + OFF_STATES;
    float* s_t      = sm + OFF_T;
    float* s_avA    = sm + OFF_AVA;
    float* s_diff   = sm + OFF_DIFF;
    float* s_w      = sm + OFF_W;
    float* s_aW1    = sm + OFF_AW1;
    float* s_dW1    = sm + OFF_DW1;
    float* s_bW1    = sm + OFF_BW1;
    float* s_act    = sm + OFF_ACT;
    float* s_pol    = sm + OFF_POL;
    float* s_W2     = sm + OFF_W2;

    const int b   = blockIdx.x;
    const int tid = threadIdx.x;

    // =========================================================================
    // Phase 0: this CTA's 64-element contribution to M = (Wq@Wk^T)/sqrt(128).
    // CTA b: row i = b>>1, cols j0..j0+63 where j0 = (b&1)*64.
    // Thread tid: output j = tid>>2, quarter q = tid&3 covers d in [32q, 32q+32).
    // =========================================================================
    {
        const int i  = b >> 1;
        const int j0 = (b & 1) * 64;
        const int j  = tid >> 2;
        const int q  = tid & 3;
        const int d0 = q * 32;
        float acc = 0.f;
        #pragma unroll
        for (int d = 0; d < 32; d += 4) {
            float4 wq = *reinterpret_cast<const float4*>(&Wq[i * OBS + d0 + d]);
            float4 wk = *reinterpret_cast<const float4*>(&Wk[(j0 + j) * OBS + d0 + d]);
            acc = fmaf(wq.x, wk.x, fmaf(wq.y, wk.y, fmaf(wq.z, wk.z, fmaf(wq.w, wk.w, acc))));
        }
        acc += __shfl_xor_sync(0xffffffffu, acc, 1);
        acc += __shfl_xor_sync(0xffffffffu, acc, 2);
        if (q == 0)
            g_M[i * OBS + j0 + j] = acc * 0.08838834764831845f;
        __threadfence();               // make this thread's M store device-visible
        __syncthreads();
        if (tid == 0) atomicAdd(&g_cnt, 1);
    }

    // ---- stage inputs ----
    {
        const float* st_b = states + (size_t)b * NA * OBS;
        for (int idx = tid; idx < NA * OBS / 4; idx += 256) {
            int i = idx >> 5, d4 = (idx & 31) * 4;
            *reinterpret_cast<float4*>(&s_states[i * S1 + d4]) =
                *reinterpret_cast<const float4*>(&st_b[i * OBS + d4]);
        }
        for (int idx = tid; idx < NA * ACT; idx += 256) {
            s_act[idx] = actions [(size_t)b * NA * ACT + idx];
            s_pol[idx] = policies[(size_t)b * NA * ACT + idx];
        }
        for (int idx = tid; idx < DH * DO; idx += 256) s_W2[idx] = W2[idx];
    }
    __syncthreads();

    // =========================================================================
    // Phase 1v: avA/diff = tanh(concat@Wv). 4 rows x 4 cols per thread.
    // (V path first: gives every CTA time to finish its M contribution.)
    // =========================================================================
    {
        const int r0 = (tid >> 5) * 4;
        const int c0 = (tid & 31) * 4;
        float4 vAcc[4];
        #pragma unroll
        for (int r = 0; r < 4; ++r) vAcc[r] = make_float4(0,0,0,0);
        for (int kk = 0; kk < OBS; kk += 4) {
            float4 sv[4];
            #pragma unroll
            for (int r = 0; r < 4; ++r)
                sv[r] = *reinterpret_cast<const float4*>(&s_states[(r0 + r) * S1 + kk]);
            #pragma unroll
            for (int t = 0; t < 4; ++t) {
                float4 wv = *reinterpret_cast<const float4*>(&Wv[(kk + t) * DV + c0]);
                #pragma unroll
                for (int r = 0; r < 4; ++r) {
                    float s = reinterpret_cast<const float*>(&sv[r])[t];
                    vAcc[r].x = fmaf(s, wv.x, vAcc[r].x);
                    vAcc[r].y = fmaf(s, wv.y, vAcc[r].y);
                    vAcc[r].z = fmaf(s, wv.z, vAcc[r].z);
                    vAcc[r].w = fmaf(s, wv.w, vAcc[r].w);
                }
            }
        }
        {   // actions tail -> avA
            float4 acc[4];
            #pragma unroll
            for (int r = 0; r < 4; ++r) acc[r] = vAcc[r];
            #pragma unroll
            for (int kk = 0; kk < ACT; ++kk) {
                float4 wv = *reinterpret_cast<const float4*>(&Wv[(OBS + kk) * DV + c0]);
                #pragma unroll
                for (int r = 0; r < 4; ++r) {
                    float a = s_act[(r0 + r) * ACT + kk];
                    acc[r].x = fmaf(a, wv.x, acc[r].x);
                    acc[r].y = fmaf(a, wv.y, acc[r].y);
                    acc[r].z = fmaf(a, wv.z, acc[r].z);
                    acc[r].w = fmaf(a, wv.w, acc[r].w);
                }
            }
            #pragma unroll
            for (int r = 0; r < 4; ++r) {
                float4 tA;
                tA.x = tanhf(acc[r].x); tA.y = tanhf(acc[r].y);
                tA.z = tanhf(acc[r].z); tA.w = tanhf(acc[r].w);
                *reinterpret_cast<float4*>(&s_avA[(r0 + r) * S1 + c0]) = tA;
            }
        }
        {   // policies tail -> diff = tanh(P) - avA
            float4 acc[4];
            #pragma unroll
            for (int r = 0; r < 4; ++r) acc[r] = vAcc[r];
            #pragma unroll
            for (int kk = 0; kk < ACT; ++kk) {
                float4 wv = *reinterpret_cast<const float4*>(&Wv[(OBS + kk) * DV + c0]);
                #pragma unroll
                for (int r = 0; r < 4; ++r) {
                    float p = s_pol[(r0 + r) * ACT + kk];
                    acc[r].x = fmaf(p, wv.x, acc[r].x);
                    acc[r].y = fmaf(p, wv.y, acc[r].y);
                    acc[r].z = fmaf(p, wv.z, acc[r].z);
                    acc[r].w = fmaf(p, wv.w, acc[r].w);
                }
            }
            #pragma unroll
            for (int r = 0; r < 4; ++r) {
                float4 tA = *reinterpret_cast<const float4*>(&s_avA[(r0 + r) * S1 + c0]);
                float4 dF;
                dF.x = tanhf(acc[r].x) - tA.x; dF.y = tanhf(acc[r].y) - tA.y;
                dF.z = tanhf(acc[r].z) - tA.z; dF.w = tanhf(acc[r].w) - tA.w;
                *reinterpret_cast<float4*>(&s_diff[(r0 + r) * S1 + c0]) = dF;
            }
        }
    }
    __syncthreads();

    // =========================================================================
    // Phase 2b: aW1 = avA@W1, dW1 = diff@W1. 2 j-rows x 4 h per thread.
    // =========================================================================
    {
        const int j0 = (tid >> 4) * 2;
        const int h0 = (tid & 15) * 4;
        float4 aA0 = make_float4(0,0,0,0), aA1 = make_float4(0,0,0,0);
        float4 aD0 = make_float4(0,0,0,0), aD1 = make_float4(0,0,0,0);
        for (int d = 0; d < DV; d += 4) {
            float4 av0 = *reinterpret_cast<const float4*>(&s_avA [ j0      * S1 + d]);
            float4 av1 = *reinterpret_cast<const float4*>(&s_avA [(j0 + 1) * S1 + d]);
            float4 df0 = *reinterpret_cast<const float4*>(&s_diff[ j0      * S1 + d]);
            float4 df1 = *reinterpret_cast<const float4*>(&s_diff[(j0 + 1) * S1 + d]);
            #pragma unroll
            for (int t = 0; t < 4; ++t) {
                float4 w1 = *reinterpret_cast<const float4*>(&W1[(d + t) * DH + h0]);
                float a0 = reinterpret_cast<const float*>(&av0)[t];
                float a1 = reinterpret_cast<const float*>(&av1)[t];
                float d0 = reinterpret_cast<const float*>(&df0)[t];
                float d1 = reinterpret_cast<const float*>(&df1)[t];
                aA0.x = fmaf(a0, w1.x, aA0.x); aA0.y = fmaf(a0, w1.y, aA0.y);
                aA0.z = fmaf(a0, w1.z, aA0.z); aA0.w = fmaf(a0, w1.w, aA0.w);
                aA1.x = fmaf(a1, w1.x, aA1.x); aA1.y = fmaf(a1, w1.y, aA1.y);
                aA1.z = fmaf(a1, w1.z, aA1.z); aA1.w = fmaf(a1, w1.w, aA1.w);
                aD0.x = fmaf(d0, w1.x, aD0.x); aD0.y = fmaf(d0, w1.y, aD0.y);
                aD0.z = fmaf(d0, w1.z, aD0.z); aD0.w = fmaf(d0, w1.w, aD0.w);
                aD1.x = fmaf(d1, w1.x, aD1.x); aD1.y = fmaf(d1, w1.y, aD1.y);
                aD1.z = fmaf(d1, w1.z, aD1.z); aD1.w = fmaf(d1, w1.w, aD1.w);
            }
        }
        *reinterpret_cast<float4*>(&s_aW1[ j0      * S2 + h0]) = aA0;
        *reinterpret_cast<float4*>(&s_aW1[(j0 + 1) * S2 + h0]) = aA1;
        *reinterpret_cast<float4*>(&s_dW1[ j0      * S2 + h0]) = aD0;
        *reinterpret_cast<float4*>(&s_dW1[(j0 + 1) * S2 + h0]) = aD1;
    }

    // ---- wait for all 256 CTAs' M contributions (normally already done) ----
    __syncthreads();
    if (tid == 0) {
        while (*((volatile int*)&g_cnt) < BATCH) { }
        __threadfence();
    }
    __syncthreads();

    // =========================================================================
    // Phase 1t: t = states @ M. 4 rows x 4 cols per thread.
    // Warp w writes s_t rows 4w..4w+3 (exactly the rows its P2a needs).
    // =========================================================================
    {
        const int r0 = (tid >> 5) * 4;
        const int c0 = (tid & 31) * 4;
        float4 acc[4];
        #pragma unroll
        for (int r = 0; r < 4; ++r) acc[r] = make_float4(0,0,0,0);
        for (int kk = 0; kk < OBS; kk += 4) {
            float4 sv[4];
            #pragma unroll
            for (int r = 0; r < 4; ++r)
                sv[r] = *reinterpret_cast<const float4*>(&s_states[(r0 + r) * S1 + kk]);
            #pragma unroll
            for (int t = 0; t < 4; ++t) {
                float4 mq = *reinterpret_cast<const float4*>(&g_M[(kk + t) * OBS + c0]);
                #pragma unroll
                for (int r = 0; r < 4; ++r) {
                    float s = reinterpret_cast<const float*>(&sv[r])[t];
                    acc[r].x = fmaf(s, mq.x, acc[r].x);
                    acc[r].y = fmaf(s, mq.y, acc[r].y);
                    acc[r].z = fmaf(s, mq.z, acc[r].z);
                    acc[r].w = fmaf(s, mq.w, acc[r].w);
                }
            }
        }
        #pragma unroll
        for (int r = 0; r < 4; ++r)
            *reinterpret_cast<float4*>(&s_t[(r0 + r) * S1 + c0]) = acc[r];
    }
    __syncwarp();   // P2a reads only this warp's s_t rows

    // =========================================================================
    // Phase 2a: score[i][j] = t[i,:] . states[j,:]; warp w owns rows 4w..4w+3
    // =========================================================================
    {
        const int i0 = (tid >> 4) * 2;
        const int j0 = (tid & 15) * 2;
        float a00 = 0.f, a01 = 0.f, a10 = 0.f, a11 = 0.f;
        for (int kk = 0; kk < OBS; kk += 4) {
            float4 q0 = *reinterpret_cast<const float4*>(&s_t[ i0      * S1 + kk]);
            float4 q1 = *reinterpret_cast<const float4*>(&s_t[(i0 + 1) * S1 + kk]);
            float4 k0 = *reinterpret_cast<const float4*>(&s_states[ j0      * S1 + kk]);
            float4 k1 = *reinterpret_cast<const float4*>(&s_states[(j0 + 1) * S1 + kk]);
            a00 = fmaf(q0.x, k0.x, fmaf(q0.y, k0.y, fmaf(q0.z, k0.z, fmaf(q0.w, k0.w, a00))));
            a01 = fmaf(q0.x, k1.x, fmaf(q0.y, k1.y, fmaf(q0.z, k1.z, fmaf(q0.w, k1.w, a01))));
            a10 = fmaf(q1.x, k0.x, fmaf(q1.y, k0.y, fmaf(q1.z, k0.z, fmaf(q1.w, k0.w, a10))));
            a11 = fmaf(q1.x, k1.x, fmaf(q1.y, k1.y, fmaf(q1.z, k1.z, fmaf(q1.w, k1.w, a11))));
        }
        s_w[i0 * NA + j0]           = a00;
        s_w[i0 * NA + j0 + 1]       = a01;
        s_w[(i0 + 1) * NA + j0]     = a10;
        s_w[(i0 + 1) * NA + j0 + 1] = a11;
    }
    __syncwarp();

    // softmax — warp w owns rows 4w..4w+3
    {
        const int warp = tid >> 5, lane = tid & 31;
        #pragma unroll
        for (int rr = 0; rr < 4; ++rr) {
            const int row = warp * 4 + rr;
            float v = s_w[row * NA + lane];
            float m = v;
            #pragma unroll
            for (int off = 16; off > 0; off >>= 1)
                m = fmaxf(m, __shfl_xor_sync(0xffffffffu, m, off));
            float e = expf(v - m);
            float s = e;
            #pragma unroll
            for (int off = 16; off > 0; off >>= 1)
                s += __shfl_xor_sync(0xffffffffu, s, off);
            float w = e / s;
            s_w[row * NA + lane] = w;
            weight_out[(size_t)b * NA * NA + row * NA + lane] = w;
        }
    }
    __syncthreads();

    // =========================================================================
    // Phase 4: bW1 = w @ aW1   [32 x 64]
    // =========================================================================
    {
        const int a0 = (tid >> 4) * 2;
        const int h0 = (tid & 15) * 4;
        float4 acc0 = make_float4(0,0,0,0), acc1 = make_float4(0,0,0,0);
        #pragma unroll
        for (int j = 0; j < NA; j += 4) {
            float4 w0 = *reinterpret_cast<const float4*>(&s_w[ a0      * NA + j]);
            float4 w1 = *reinterpret_cast<const float4*>(&s_w[(a0 + 1) * NA + j]);
            #pragma unroll
            for (int t = 0; t < 4; ++t) {
                float4 aw = *reinterpret_cast<const float4*>(&s_aW1[(j + t) * S2 + h0]);
                float v0 = reinterpret_cast<const float*>(&w0)[t];
                float v1 = reinterpret_cast<const float*>(&w1)[t];
                acc0.x = fmaf(v0, aw.x, acc0.x); acc0.y = fmaf(v0, aw.y, acc0.y);
                acc0.z = fmaf(v0, aw.z, acc0.z); acc0.w = fmaf(v0, aw.w, acc0.w);
                acc1.x = fmaf(v1, aw.x, acc1.x); acc1.y = fmaf(v1, aw.y, acc1.y);
                acc1.z = fmaf(v1, aw.z, acc1.z); acc1.w = fmaf(v1, aw.w, acc1.w);
            }
        }
        *reinterpret_cast<float4*>(&s_bW1[ a0      * S2 + h0]) = acc0;
        *reinterpret_cast<float4*>(&s_bW1[(a0 + 1) * S2 + h0]) = acc1;
    }
    __syncthreads();

    // =========================================================================
    // Phase 5: per (a,c): h = leaky(bW1[a] + w*dW1[c]); out = h @ W2.
    // =========================================================================
    {
        const int a0 = tid >> 5;      // 0..7
        const int c  = tid & 31;
        float wk[4];
        #pragma unroll
        for (int k = 0; k < 4; ++k) wk[k] = s_w[(a0 + 8 * k) * NA + c];

        float4 accL[4], accH[4];
        #pragma unroll
        for (int k = 0; k < 4; ++k) {
            accL[k] = make_float4(0,0,0,0);
            accH[k] = make_float4(0,0,0,0);
        }
        for (int h = 0; h < DH; h += 4) {
            float4 dq = *reinterpret_cast<const float4*>(&s_dW1[c * S2 + h]);
            float4 w2lo[4], w2hi[4];
            #pragma unroll
            for (int t = 0; t < 4; ++t) {
                w2lo[t] = *reinterpret_cast<const float4*>(&s_W2[(h + t) * DO]);
                w2hi[t] = *reinterpret_cast<const float4*>(&s_W2[(h + t) * DO + 4]);
            }
            #pragma unroll
            for (int k = 0; k < 4; ++k) {
                float4 bq = *reinterpret_cast<const float4*>(&s_bW1[(a0 + 8 * k) * S2 + h]);
                #pragma unroll
                for (int t = 0; t < 4; ++t) {
                    float x = fmaf(wk[k],
                                   reinterpret_cast<const float*>(&dq)[t],
                                   reinterpret_cast<const float*>(&bq)[t]);
                    x = fmaxf(x, 0.01f * x);   // leaky_relu(0.01)
                    accL[k].x = fmaf(x, w2lo[t].x, accL[k].x);
                    accL[k].y = fmaf(x, w2lo[t].y, accL[k].y);
                    accL[k].z = fmaf(x, w2lo[t].z, accL[k].z);
                    accL[k].w = fmaf(x, w2lo[t].w, accL[k].w);
                    accH[k].x = fmaf(x, w2hi[t].x, accH[k].x);
                    accH[k].y = fmaf(x, w2hi[t].y, accH[k].y);
                    accH[k].z = fmaf(x, w2hi[t].z, accH[k].z);
                    accH[k].w = fmaf(x, w2hi[t].w, accH[k].w);
                }
            }
        }
        #pragma unroll
        for (int k = 0; k < 4; ++k) {
            float4* outp = reinterpret_cast<float4*>(
                value_out + (((size_t)b * NA + (a0 + 8 * k)) * NA + c) * DO);
            outp[0] = accL[k];
            outp[1] = accH[k];
        }
    }
}

extern "C" void kernel_launch(void* const* d_in, const int* in_sizes, int n_in,
                              void* d_out, int out_size) {
    const float* states   = (const float*)d_in[0];
    const float* policies = (const float*)d_in[1];
    const float* actions  = (const float*)d_in[2];
    const float* Wk       = (const float*)d_in[3];
    const float* Wq       = (const float*)d_in[4];
    const float* Wv       = (const float*)d_in[5];
    const float* W1       = (const float*)d_in[6];
    const float* W2       = (const float*)d_in[7];

    float* value_out  = (float*)d_out;                              // [B,N,N,8]
    float* weight_out = value_out + (size_t)BATCH * NA * NA * DO;   // [B,N,N]

    // reset the arrival counter each launch (captured as a memset node)
    void* cnt_addr = nullptr;
    cudaGetSymbolAddress(&cnt_addr, g_cnt);
    cudaMemsetAsync(cnt_addr, 0, sizeof(int));

    cudaFuncSetAttribute(critic_kernel,
                         cudaFuncAttributeMaxDynamicSharedMemorySize, SMEM_BYTES);
    critic_kernel<<<BATCH, 256, SMEM_BYTES>>>(
        states, policies, actions, Wq, Wk, Wv, W1, W2, value_out, weight_out);
}

// round 14
// speedup vs baseline: 1.1865x; 1.1089x over previous
#include <cuda_runtime.h>
#include <math.h>
#include <cstdint>

#define BATCH 256
#define NA    32
#define OBS   128
#define ACT   8
#define DV    128
#define DH    64
#define DO    8
#define S1    132   // padded stride (floats) for 128-wide rows, float4-aligned
#define S2    68    // padded stride for 64-wide rows

// ---- SMEM layout (floats) ----
#define OFF_STATES 0
#define OFF_T      (OFF_STATES + NA*S1)
#define OFF_AVA    (OFF_T + NA*S1)
#define OFF_DIFF   (OFF_AVA + NA*S1)
#define OFF_W      (OFF_DIFF + NA*S1)
#define OFF_AW1    (OFF_W + NA*NA)
#define OFF_DW1    (OFF_AW1 + NA*S2)
#define OFF_BW1    (OFF_DW1 + NA*S2)
#define OFF_ACT    (OFF_BW1 + NA*S2)
#define OFF_POL    (OFF_ACT + NA*ACT)
#define OFF_W2     (OFF_POL + NA*ACT)
#define SMEM_FLOATS (OFF_W2 + DH*DO)
#define SMEM_BYTES  (SMEM_FLOATS * 4)

__device__ float g_M[OBS * OBS];   // (Wq @ Wk^T) / sqrt(DK), contract over DK

// ---------------------------------------------------------------------------
// M[i][j] = (sum_d Wq[i][d] * Wk[j][d]) / sqrt(128)
// Fast split-K version: 256 CTAs x 256 thr. CTA bb: row i = bb>>1, 64 cols
// starting at j0 = (bb&1)*64. Each output computed by 4 threads (32-deep
// chains) + 2 shfl reduces. No smem, no barriers.
// ---------------------------------------------------------------------------
__global__ __launch_bounds__(256)
void compute_M_kernel(const float* __restrict__ Wq,
                      const float* __restrict__ Wk) {
    const int bb  = blockIdx.x;
    const int i   = bb >> 1;
    const int j0  = (bb & 1) * 64;
    const int tid = threadIdx.x;
    const int j   = tid >> 2;        // 0..63
    const int q   = tid & 3;         // K-quarter
    const int d0  = q * 32;

    float acc = 0.f;
    #pragma unroll
    for (int d = 0; d < 32; d += 4) {
        float4 wq = *reinterpret_cast<const float4*>(&Wq[i * OBS + d0 + d]);
        float4 wk = *reinterpret_cast<const float4*>(&Wk[(j0 + j) * OBS + d0 + d]);
        acc = fmaf(wq.x, wk.x, fmaf(wq.y, wk.y, fmaf(wq.z, wk.z, fmaf(wq.w, wk.w, acc))));
    }
    acc += __shfl_xor_sync(0xffffffffu, acc, 1);
    acc += __shfl_xor_sync(0xffffffffu, acc, 2);
    if (q == 0)
        g_M[i * OBS + j0 + j] = acc * 0.08838834764831845f;
}

// ---------------------------------------------------------------------------
// Main fused kernel (byte-identical to the proven 53.3us R5 version):
// one CTA per batch element, 256 threads, 2 CTAs/SM.
// ---------------------------------------------------------------------------
__global__ __launch_bounds__(256, 2)
void critic_kernel(const float* __restrict__ states,
                   const float* __restrict__ policies,
                   const float* __restrict__ actions,
                   const float* __restrict__ Wv,
                   const float* __restrict__ W1,
                   const float* __restrict__ W2,
                   float* __restrict__ value_out,
                   float* __restrict__ weight_out)
{
    extern __shared__ float sm[];
    float* s_states = sm + OFF_STATES;
    float* s_t      = sm + OFF_T;
    float* s_avA    = sm + OFF_AVA;
    float* s_diff   = sm + OFF_DIFF;
    float* s_w      = sm + OFF_W;
    float* s_aW1    = sm + OFF_AW1;
    float* s_dW1    = sm + OFF_DW1;
    float* s_bW1    = sm + OFF_BW1;
    float* s_act    = sm + OFF_ACT;
    float* s_pol    = sm + OFF_POL;
    float* s_W2     = sm + OFF_W2;

    const int b   = blockIdx.x;
    const int tid = threadIdx.x;

    // ---- stage inputs ----
    {
        const float* st_b = states + (size_t)b * NA * OBS;
        for (int idx = tid; idx < NA * OBS / 4; idx += 256) {
            int i = idx >> 5, d4 = (idx & 31) * 4;
            *reinterpret_cast<float4*>(&s_states[i * S1 + d4]) =
                *reinterpret_cast<const float4*>(&st_b[i * OBS + d4]);
        }
        for (int idx = tid; idx < NA * ACT; idx += 256) {
            s_act[idx] = actions [(size_t)b * NA * ACT + idx];
            s_pol[idx] = policies[(size_t)b * NA * ACT + idx];
        }
        for (int idx = tid; idx < DH * DO; idx += 256) s_W2[idx] = W2[idx];
    }
    __syncthreads();

    // =========================================================================
    // Phase 1: t = states@M and avA/diff = tanh(concat@Wv).
    // Warp w owns cols [16w,16w+16) for ALL 32 rows.
    // Lane: c0 = 16w + (l&3)*4 ; rows {g, g+8, g+16, g+24}, g = l>>2
    // =========================================================================
    {
        const int w  = tid >> 5;
        const int l  = tid & 31;
        const int g  = l >> 2;
        const int c0 = w * 16 + (l & 3) * 4;

        float4 tAcc[4], vAcc[4];
        #pragma unroll
        for (int m = 0; m < 4; ++m) {
            tAcc[m] = make_float4(0.f, 0.f, 0.f, 0.f);
            vAcc[m] = make_float4(0.f, 0.f, 0.f, 0.f);
        }
        for (int kk = 0; kk < OBS; kk += 4) {
            float4 sv[4];
            #pragma unroll
            for (int m = 0; m < 4; ++m)
                sv[m] = *reinterpret_cast<const float4*>(&s_states[(g + 8 * m) * S1 + kk]);
            #pragma unroll
            for (int t = 0; t < 4; ++t) {
                float4 mq = *reinterpret_cast<const float4*>(&g_M[(kk + t) * OBS + c0]);
                float4 wv = *reinterpret_cast<const float4*>(&Wv [(kk + t) * DV  + c0]);
                #pragma unroll
                for (int m = 0; m < 4; ++m) {
                    float s = reinterpret_cast<const float*>(&sv[m])[t];
                    tAcc[m].x = fmaf(s, mq.x, tAcc[m].x);
                    tAcc[m].y = fmaf(s, mq.y, tAcc[m].y);
                    tAcc[m].z = fmaf(s, mq.z, tAcc[m].z);
                    tAcc[m].w = fmaf(s, mq.w, tAcc[m].w);
                    vAcc[m].x = fmaf(s, wv.x, vAcc[m].x);
                    vAcc[m].y = fmaf(s, wv.y, vAcc[m].y);
                    vAcc[m].z = fmaf(s, wv.z, vAcc[m].z);
                    vAcc[m].w = fmaf(s, wv.w, vAcc[m].w);
                }
            }
        }
        #pragma unroll
        for (int m = 0; m < 4; ++m)
            *reinterpret_cast<float4*>(&s_t[(g + 8 * m) * S1 + c0]) = tAcc[m];

        // action/policy tail (8 extra K) on the shared states partial
        float4 accA[4], accP[4];
        #pragma unroll
        for (int m = 0; m < 4; ++m) { accA[m] = vAcc[m]; accP[m] = vAcc[m]; }
        #pragma unroll
        for (int kk = 0; kk < ACT; ++kk) {
            float4 wv = *reinterpret_cast<const float4*>(&Wv[(OBS + kk) * DV + c0]);
            #pragma unroll
            for (int m = 0; m < 4; ++m) {
                float a = s_act[(g + 8 * m) * ACT + kk];
                float p = s_pol[(g + 8 * m) * ACT + kk];
                accA[m].x = fmaf(a, wv.x, accA[m].x);
                accA[m].y = fmaf(a, wv.y, accA[m].y);
                accA[m].z = fmaf(a, wv.z, accA[m].z);
                accA[m].w = fmaf(a, wv.w, accA[m].w);
                accP[m].x = fmaf(p, wv.x, accP[m].x);
                accP[m].y = fmaf(p, wv.y, accP[m].y);
                accP[m].z = fmaf(p, wv.z, accP[m].z);
                accP[m].w = fmaf(p, wv.w, accP[m].w);
            }
        }
        #pragma unroll
        for (int m = 0; m < 4; ++m) {
            float4 tA, dF;
            tA.x = tanhf(accA[m].x); tA.y = tanhf(accA[m].y);
            tA.z = tanhf(accA[m].z); tA.w = tanhf(accA[m].w);
            dF.x = tanhf(accP[m].x) - tA.x; dF.y = tanhf(accP[m].y) - tA.y;
            dF.z = tanhf(accP[m].z) - tA.z; dF.w = tanhf(accP[m].w) - tA.w;
            *reinterpret_cast<float4*>(&s_avA [(g + 8 * m) * S1 + c0]) = tA;
            *reinterpret_cast<float4*>(&s_diff[(g + 8 * m) * S1 + c0]) = dF;
        }
    }
    __syncthreads();

    // =========================================================================
    // Phase 2a: score[i][j] = t[i,:] . states[j,:]  (scale folded into M).
    // Warp w produces rows 4w..4w+3 entirely locally.
    // =========================================================================
    {
        const int i0 = (tid >> 4) * 2;
        const int j0 = (tid & 15) * 2;
        float a00 = 0.f, a01 = 0.f, a10 = 0.f, a11 = 0.f;
        for (int kk = 0; kk < OBS; kk += 4) {
            float4 q0 = *reinterpret_cast<const float4*>(&s_t[ i0      * S1 + kk]);
            float4 q1 = *reinterpret_cast<const float4*>(&s_t[(i0 + 1) * S1 + kk]);
            float4 k0 = *reinterpret_cast<const float4*>(&s_states[ j0      * S1 + kk]);
            float4 k1 = *reinterpret_cast<const float4*>(&s_states[(j0 + 1) * S1 + kk]);
            a00 = fmaf(q0.x, k0.x, fmaf(q0.y, k0.y, fmaf(q0.z, k0.z, fmaf(q0.w, k0.w, a00))));
            a01 = fmaf(q0.x, k1.x, fmaf(q0.y, k1.y, fmaf(q0.z, k1.z, fmaf(q0.w, k1.w, a01))));
            a10 = fmaf(q1.x, k0.x, fmaf(q1.y, k0.y, fmaf(q1.z, k0.z, fmaf(q1.w, k0.w, a10))));
            a11 = fmaf(q1.x, k1.x, fmaf(q1.y, k1.y, fmaf(q1.z, k1.z, fmaf(q1.w, k1.w, a11))));
        }
        s_w[i0 * NA + j0]           = a00;
        s_w[i0 * NA + j0 + 1]       = a01;
        s_w[(i0 + 1) * NA + j0]     = a10;
        s_w[(i0 + 1) * NA + j0 + 1] = a11;
    }
    __syncwarp();

    // =========================================================================
    // Phase 2a': softmax — warp w owns rows 4w..4w+3 (warp-local sync only)
    // =========================================================================
    {
        const int warp = tid >> 5, lane = tid & 31;
        #pragma unroll
        for (int rr = 0; rr < 4; ++rr) {
            const int row = warp * 4 + rr;
            float v = s_w[row * NA + lane];
            float m = v;
            #pragma unroll
            for (int off = 16; off > 0; off >>= 1)
                m = fmaxf(m, __shfl_xor_sync(0xffffffffu, m, off));
            float e = expf(v - m);
            float s = e;
            #pragma unroll
            for (int off = 16; off > 0; off >>= 1)
                s += __shfl_xor_sync(0xffffffffu, s, off);
            float w = e / s;
            s_w[row * NA + lane] = w;
            weight_out[(size_t)b * NA * NA + row * NA + lane] = w;
        }
    }

    // =========================================================================
    // Phase 2b: aW1 = avA@W1, dW1 = diff@W1. 2 j-rows x 4 h per thread.
    // =========================================================================
    {
        const int j0 = (tid >> 4) * 2;
        const int h0 = (tid & 15) * 4;
        float4 aA0 = make_float4(0,0,0,0), aA1 = make_float4(0,0,0,0);
        float4 aD0 = make_float4(0,0,0,0), aD1 = make_float4(0,0,0,0);
        for (int d = 0; d < DV; d += 4) {
            float4 av0 = *reinterpret_cast<const float4*>(&s_avA [ j0      * S1 + d]);
            float4 av1 = *reinterpret_cast<const float4*>(&s_avA [(j0 + 1) * S1 + d]);
            float4 df0 = *reinterpret_cast<const float4*>(&s_diff[ j0      * S1 + d]);
            float4 df1 = *reinterpret_cast<const float4*>(&s_diff[(j0 + 1) * S1 + d]);
            #pragma unroll
            for (int t = 0; t < 4; ++t) {
                float4 w1 = *reinterpret_cast<const float4*>(&W1[(d + t) * DH + h0]);
                float a0 = reinterpret_cast<const float*>(&av0)[t];
                float a1 = reinterpret_cast<const float*>(&av1)[t];
                float d0 = reinterpret_cast<const float*>(&df0)[t];
                float d1 = reinterpret_cast<const float*>(&df1)[t];
                aA0.x = fmaf(a0, w1.x, aA0.x); aA0.y = fmaf(a0, w1.y, aA0.y);
                aA0.z = fmaf(a0, w1.z, aA0.z); aA0.w = fmaf(a0, w1.w, aA0.w);
                aA1.x = fmaf(a1, w1.x, aA1.x); aA1.y = fmaf(a1, w1.y, aA1.y);
                aA1.z = fmaf(a1, w1.z, aA1.z); aA1.w = fmaf(a1, w1.w, aA1.w);
                aD0.x = fmaf(d0, w1.x, aD0.x); aD0.y = fmaf(d0, w1.y, aD0.y);
                aD0.z = fmaf(d0, w1.z, aD0.z); aD0.w = fmaf(d0, w1.w, aD0.w);
                aD1.x = fmaf(d1, w1.x, aD1.x); aD1.y = fmaf(d1, w1.y, aD1.y);
                aD1.z = fmaf(d1, w1.z, aD1.z); aD1.w = fmaf(d1, w1.w, aD1.w);
            }
        }
        *reinterpret_cast<float4*>(&s_aW1[ j0      * S2 + h0]) = aA0;
        *reinterpret_cast<float4*>(&s_aW1[(j0 + 1) * S2 + h0]) = aA1;
        *reinterpret_cast<float4*>(&s_dW1[ j0      * S2 + h0]) = aD0;
        *reinterpret_cast<float4*>(&s_dW1[(j0 + 1) * S2 + h0]) = aD1;
    }
    __syncthreads();

    // =========================================================================
    // Phase 4: bW1 = w @ aW1   [32 x 64]
    // =========================================================================
    {
        const int a0 = (tid >> 4) * 2;
        const int h0 = (tid & 15) * 4;
        float4 acc0 = make_float4(0,0,0,0), acc1 = make_float4(0,0,0,0);
        #pragma unroll
        for (int j = 0; j < NA; j += 4) {
            float4 w0 = *reinterpret_cast<const float4*>(&s_w[ a0      * NA + j]);
            float4 w1 = *reinterpret_cast<const float4*>(&s_w[(a0 + 1) * NA + j]);
            #pragma unroll
            for (int t = 0; t < 4; ++t) {
                float4 aw = *reinterpret_cast<const float4*>(&s_aW1[(j + t) * S2 + h0]);
                float v0 = reinterpret_cast<const float*>(&w0)[t];
                float v1 = reinterpret_cast<const float*>(&w1)[t];
                acc0.x = fmaf(v0, aw.x, acc0.x); acc0.y = fmaf(v0, aw.y, acc0.y);
                acc0.z = fmaf(v0, aw.z, acc0.z); acc0.w = fmaf(v0, aw.w, acc0.w);
                acc1.x = fmaf(v1, aw.x, acc1.x); acc1.y = fmaf(v1, aw.y, acc1.y);
                acc1.z = fmaf(v1, aw.z, acc1.z); acc1.w = fmaf(v1, aw.w, acc1.w);
            }
        }
        *reinterpret_cast<float4*>(&s_bW1[ a0      * S2 + h0]) = acc0;
        *reinterpret_cast<float4*>(&s_bW1[(a0 + 1) * S2 + h0]) = acc1;
    }
    __syncthreads();

    // =========================================================================
    // Phase 5: per (a,c): h = leaky(bW1[a] + w*dW1[c]); out = h @ W2.
    // 4 a-values per thread so dW1/W2 loads amortize.
    // =========================================================================
    {
        const int a0 = tid >> 5;      // 0..7
        const int c  = tid & 31;      // 0..31
        float wk[4];
        #pragma unroll
        for (int k = 0; k < 4; ++k) wk[k] = s_w[(a0 + 8 * k) * NA + c];

        float4 accL[4], accH[4];
        #pragma unroll
        for (int k = 0; k < 4; ++k) {
            accL[k] = make_float4(0,0,0,0);
            accH[k] = make_float4(0,0,0,0);
        }
        for (int h = 0; h < DH; h += 4) {
            float4 dq = *reinterpret_cast<const float4*>(&s_dW1[c * S2 + h]);
            float4 w2lo[4], w2hi[4];
            #pragma unroll
            for (int t = 0; t < 4; ++t) {
                w2lo[t] = *reinterpret_cast<const float4*>(&s_W2[(h + t) * DO]);
                w2hi[t] = *reinterpret_cast<const float4*>(&s_W2[(h + t) * DO + 4]);
            }
            #pragma unroll
            for (int k = 0; k < 4; ++k) {
                float4 bq = *reinterpret_cast<const float4*>(&s_bW1[(a0 + 8 * k) * S2 + h]);
                #pragma unroll
                for (int t = 0; t < 4; ++t) {
                    float x = fmaf(wk[k],
                                   reinterpret_cast<const float*>(&dq)[t],
                                   reinterpret_cast<const float*>(&bq)[t]);
                    x = fmaxf(x, 0.01f * x);   // leaky_relu(0.01)
                    accL[k].x = fmaf(x, w2lo[t].x, accL[k].x);
                    accL[k].y = fmaf(x, w2lo[t].y, accL[k].y);
                    accL[k].z = fmaf(x, w2lo[t].z, accL[k].z);
                    accL[k].w = fmaf(x, w2lo[t].w, accL[k].w);
                    accH[k].x = fmaf(x, w2hi[t].x, accH[k].x);
                    accH[k].y = fmaf(x, w2hi[t].y, accH[k].y);
                    accH[k].z = fmaf(x, w2hi[t].z, accH[k].z);
                    accH[k].w = fmaf(x, w2hi[t].w, accH[k].w);
                }
            }
        }
        #pragma unroll
        for (int k = 0; k < 4; ++k) {
            float4* outp = reinterpret_cast<float4*>(
                value_out + (((size_t)b * NA + (a0 + 8 * k)) * NA + c) * DO);
            outp[0] = accL[k];
            outp[1] = accH[k];
        }
    }
}

extern "C" void kernel_launch(void* const* d_in, const int* in_sizes, int n_in,
                              void* d_out, int out_size) {
    const float* states   = (const float*)d_in[0];
    const float* policies = (const float*)d_in[1];
    const float* actions  = (const float*)d_in[2];
    const float* Wk       = (const float*)d_in[3];
    const float* Wq       = (const float*)d_in[4];
    const float* Wv       = (const float*)d_in[5];
    const float* W1       = (const float*)d_in[6];
    const float* W2       = (const float*)d_in[7];

    float* value_out  = (float*)d_out;                              // [B,N,N,8]
    float* weight_out = value_out + (size_t)BATCH * NA * NA * DO;   // [B,N,N]

    compute_M_kernel<<<256, 256>>>(Wq, Wk);

    cudaFuncSetAttribute(critic_kernel,
                         cudaFuncAttributeMaxDynamicSharedMemorySize, SMEM_BYTES);
    critic_kernel<<<BATCH, 256, SMEM_BYTES>>>(
        states, policies, actions, Wv, W1, W2, value_out, weight_out);
}